// round 3
// baseline (speedup 1.0000x reference)
#include <cuda_runtime.h>
#include <cstddef>

// ---------------- problem constants ----------------
#define NB_N   100000
#define NS_N   50000
#define D_N    128
#define NHEADS 8
#define E_BB_N 800000
#define E_SB_N 400000
#define E_BS_N 400000

// ---------------- device scratch (static; no allocation) ----------------
__device__ float g_xb0[(size_t)NB_N * D_N];
__device__ float g_xb1[(size_t)NB_N * D_N];
__device__ float g_xs0[(size_t)NS_N * D_N];

__device__ float g_acc_bb[(size_t)NB_N * D_N];
__device__ float g_acc_sb[(size_t)NB_N * D_N];
__device__ float g_acc_bs[(size_t)NS_N * D_N];

__device__ float g_cnt_bb[NB_N];
__device__ float g_cnt_sb[NB_N];
__device__ float g_cnt_bs[NS_N];
__device__ float g_inv_bb[NB_N];
__device__ float g_inv_sb[NB_N];
__device__ float g_inv_bs[NS_N];

// combined weights: b-dst: [2][384][128], s-dst: [2][256][128]
__device__ float g_Wb[2][384 * 128];
__device__ float g_Bb[2][128];
__device__ float g_Ws[2][256 * 128];
__device__ float g_Bs[2][128];

// ---------------- helpers ----------------
__global__ void zero4_kernel(float4* __restrict__ p, int n4) {
    int i = blockIdx.x * blockDim.x + threadIdx.x;
    if (i < n4) p[i] = make_float4(0.f, 0.f, 0.f, 0.f);
}

__global__ void count_kernel(const int* __restrict__ dst, float* __restrict__ cnt, int E) {
    int e = blockIdx.x * blockDim.x + threadIdx.x;
    if (e < E) atomicAdd(cnt + dst[e], 1.0f);
}

__global__ void inv_kernel(const float* __restrict__ cnt, float* __restrict__ inv, int n) {
    int i = blockIdx.x * blockDim.x + threadIdx.x;
    if (i < n) inv[i] = 1.0f / fmaxf(cnt[i], 1.0f);
}

// one warp per edge: gather 128 floats from x[src], vectored red.add into acc[dst]
__global__ void scatter_kernel(const float* __restrict__ x,
                               const int* __restrict__ src,
                               const int* __restrict__ dst,
                               float* __restrict__ acc, int E) {
    int w    = (blockIdx.x * blockDim.x + threadIdx.x) >> 5;
    int lane = threadIdx.x & 31;
    if (w >= E) return;
    int s = src[w];
    int d = dst[w];
    float4 v = reinterpret_cast<const float4*>(x + (size_t)s * D_N)[lane];
    float* p = acc + (size_t)d * D_N + lane * 4;
    asm volatile("red.global.add.v4.f32 [%0], {%1, %2, %3, %4};"
                 :: "l"(p), "f"(v.x), "f"(v.y), "f"(v.z), "f"(v.w) : "memory");
}

// ---------------- weight prep ----------------
// g_Wb[l] rows: [0,128)=Wl[l,0]; [128,256)=Wl[l,1]; [256,384)=Wr[l,0]+Wr[l,1]
__global__ void prep_wb_kernel(const float* __restrict__ Wl, const float* __restrict__ bl,
                               const float* __restrict__ Wr) {
    int idx = blockIdx.x * blockDim.x + threadIdx.x;
    const int total = 2 * 384 * 128;
    if (idx < total) {
        int l = idx / (384 * 128);
        int r = idx % (384 * 128);
        int k = r / 128, n = r % 128;
        float v;
        if (k < 128)      v = Wl[((size_t)(l * 3 + 0) * 128 + k) * 128 + n];
        else if (k < 256) v = Wl[((size_t)(l * 3 + 1) * 128 + (k - 128)) * 128 + n];
        else              v = Wr[((size_t)(l * 3 + 0) * 128 + (k - 256)) * 128 + n]
                            + Wr[((size_t)(l * 3 + 1) * 128 + (k - 256)) * 128 + n];
        g_Wb[l][r] = v;
    }
    if (idx < 2 * 128) {
        int l = idx / 128, n = idx % 128;
        g_Bb[l][n] = bl[(l * 3 + 0) * 128 + n] + bl[(l * 3 + 1) * 128 + n];
    }
}

// g_Ws[l] rows: [0,128)=Wl[l,2]; [128,256)=Wr[l,2]
__global__ void prep_ws_kernel(const float* __restrict__ Wl, const float* __restrict__ bl,
                               const float* __restrict__ Wr) {
    int idx = blockIdx.x * blockDim.x + threadIdx.x;
    const int total = 2 * 256 * 128;
    if (idx < total) {
        int l = idx / (256 * 128);
        int r = idx % (256 * 128);
        int k = r / 128, n = r % 128;
        float v;
        if (k < 128) v = Wl[((size_t)(l * 3 + 2) * 128 + k) * 128 + n];
        else         v = Wr[((size_t)(l * 3 + 2) * 128 + (k - 128)) * 128 + n];
        g_Ws[l][r] = v;
    }
    if (idx < 2 * 128) {
        int l = idx / 128, n = idx % 128;
        g_Bs[l][n] = bl[(l * 3 + 2) * 128 + n];
    }
}

// ---------------- fused segmented GEMM + bias + leaky_relu ----------------
// out[M,128] = leaky( [A0*s0 | A1*s1 | A2*s2] @ W[nseg*128,128] + bias )
// scale pointer == nullptr means scale 1.0 (raw features)
__global__ void __launch_bounds__(256)
gemm_fused_kernel(const float* __restrict__ A0, const float* __restrict__ A1,
                  const float* __restrict__ A2,
                  const float* __restrict__ s0, const float* __restrict__ s1,
                  const float* __restrict__ s2,
                  const float* __restrict__ W, const float* __restrict__ bias,
                  float* __restrict__ out, int M, int nseg) {
    __shared__ __align__(16) float As[16][128];   // [k][row]
    __shared__ __align__(16) float Bs[16][128];   // [k][col]
    __shared__ float inv_s[3][128];

    const int tid  = threadIdx.x;
    const int row0 = blockIdx.x * 128;
    const int ty   = tid >> 4;       // 0..15
    const int tx   = tid & 15;       // 0..15

    if (tid < 128) {
        int r = row0 + tid;
        bool ok = r < M;
        inv_s[0][tid] = (s0 && ok) ? s0[r] : 1.0f;
        inv_s[1][tid] = (s1 && ok) ? s1[r] : 1.0f;
        inv_s[2][tid] = (s2 && ok) ? s2[r] : 1.0f;
    }
    __syncthreads();

    float acc[8][8] = {};

    for (int seg = 0; seg < nseg; ++seg) {
        const float* Ab = (seg == 0) ? A0 : ((seg == 1) ? A1 : A2);
        for (int t = 0; t < 8; ++t) {
            const int ks = t * 16;
            // --- load A tile (128 rows x 16 k), transpose into As[k][row] ---
            #pragma unroll
            for (int l = 0; l < 2; ++l) {
                int f  = tid + l * 256;        // float4 index, 0..511
                int r  = f >> 2;               // row 0..127
                int kc = (f & 3) * 4;          // k sub-offset 0,4,8,12
                int gr = row0 + r;
                float4 v = make_float4(0.f, 0.f, 0.f, 0.f);
                if (gr < M)
                    v = *reinterpret_cast<const float4*>(Ab + (size_t)gr * 128 + ks + kc);
                float sc = inv_s[seg][r];
                As[kc + 0][r] = v.x * sc;
                As[kc + 1][r] = v.y * sc;
                As[kc + 2][r] = v.z * sc;
                As[kc + 3][r] = v.w * sc;
            }
            // --- load B tile: W rows [seg*128+ks, +16), all 128 cols ---
            const int kbase = seg * 128 + ks;
            #pragma unroll
            for (int l = 0; l < 2; ++l) {
                int f  = tid + l * 256;
                int kk = f >> 5;
                int nc = (f & 31) * 4;
                *reinterpret_cast<float4*>(&Bs[kk][nc]) =
                    *reinterpret_cast<const float4*>(W + (size_t)(kbase + kk) * 128 + nc);
            }
            __syncthreads();
            // --- compute ---
            #pragma unroll
            for (int kk = 0; kk < 16; ++kk) {
                float4 a0 = *reinterpret_cast<const float4*>(&As[kk][ty * 8]);
                float4 a1 = *reinterpret_cast<const float4*>(&As[kk][ty * 8 + 4]);
                float4 b0 = *reinterpret_cast<const float4*>(&Bs[kk][tx * 8]);
                float4 b1 = *reinterpret_cast<const float4*>(&Bs[kk][tx * 8 + 4]);
                float a[8] = {a0.x, a0.y, a0.z, a0.w, a1.x, a1.y, a1.z, a1.w};
                float b[8] = {b0.x, b0.y, b0.z, b0.w, b1.x, b1.y, b1.z, b1.w};
                #pragma unroll
                for (int i = 0; i < 8; ++i)
                    #pragma unroll
                    for (int j = 0; j < 8; ++j)
                        acc[i][j] += a[i] * b[j];
            }
            __syncthreads();
        }
    }

    // --- epilogue: bias + leaky_relu, vectorized store ---
    #pragma unroll
    for (int i = 0; i < 8; ++i) {
        int r = row0 + ty * 8 + i;
        if (r < M) {
            #pragma unroll
            for (int jv = 0; jv < 2; ++jv) {
                float4 o;
                float* po = &o.x;
                #pragma unroll
                for (int q = 0; q < 4; ++q) {
                    int c = tx * 8 + jv * 4 + q;
                    float v = acc[i][jv * 4 + q] + bias[c];
                    po[q] = v > 0.f ? v : 0.01f * v;
                }
                *reinterpret_cast<float4*>(out + (size_t)r * 128 + tx * 8 + jv * 4) = o;
            }
        }
    }
}

// ---------------- classification head: out[n,h] = x[n]·Wh[h] + bh[h] ----------------
__global__ void head_kernel(const float* __restrict__ x, const float* __restrict__ Wh,
                            const float* __restrict__ bh, float* __restrict__ out) {
    __shared__ float wsh[NHEADS][128];
    __shared__ float bsh[NHEADS];
    int tid = threadIdx.x;
    for (int i = tid; i < NHEADS * 128; i += blockDim.x) wsh[i >> 7][i & 127] = Wh[i];
    if (tid < NHEADS) bsh[tid] = bh[tid];
    __syncthreads();

    int node = blockIdx.x * (blockDim.x >> 5) + (tid >> 5);
    int lane = tid & 31;
    if (node >= NB_N) return;
    float4 xv = *reinterpret_cast<const float4*>(x + (size_t)node * 128 + lane * 4);
    #pragma unroll
    for (int h = 0; h < NHEADS; ++h) {
        float4 wv = *reinterpret_cast<const float4*>(&wsh[h][lane * 4]);
        float p = xv.x * wv.x + xv.y * wv.y + xv.z * wv.z + xv.w * wv.w;
        #pragma unroll
        for (int o = 16; o > 0; o >>= 1) p += __shfl_down_sync(0xffffffffu, p, o);
        if (lane == 0) out[(size_t)node * NHEADS + h] = p + bsh[h];
    }
}

// ---------------- host launch ----------------
extern "C" void kernel_launch(void* const* d_in, const int* in_sizes, int n_in,
                              void* d_out, int out_size) {
    (void)in_sizes; (void)n_in; (void)out_size;
    const float* x_b  = (const float*)d_in[0];
    const float* x_s  = (const float*)d_in[1];
    const float* Wl   = (const float*)d_in[2];
    const float* bl   = (const float*)d_in[3];
    const float* Wr   = (const float*)d_in[4];
    const float* Wh   = (const float*)d_in[5];
    const float* bh   = (const float*)d_in[6];
    // JAX x64 is disabled by default -> edge indices are int32, not int64
    const int*   ei_bb = (const int*)d_in[7];
    const int*   ei_sb = (const int*)d_in[8];
    const int*   ei_bs = (const int*)d_in[9];

    // resolve device-global addresses (queries only; capture-safe)
    void *p_xb0, *p_xb1, *p_xs0, *p_abb, *p_asb, *p_abs;
    void *p_cbb, *p_csb, *p_cbs, *p_ibb, *p_isb, *p_ibs;
    void *p_Wb, *p_Bb, *p_Ws, *p_Bs;
    cudaGetSymbolAddress(&p_xb0, g_xb0);  cudaGetSymbolAddress(&p_xb1, g_xb1);
    cudaGetSymbolAddress(&p_xs0, g_xs0);
    cudaGetSymbolAddress(&p_abb, g_acc_bb); cudaGetSymbolAddress(&p_asb, g_acc_sb);
    cudaGetSymbolAddress(&p_abs, g_acc_bs);
    cudaGetSymbolAddress(&p_cbb, g_cnt_bb); cudaGetSymbolAddress(&p_csb, g_cnt_sb);
    cudaGetSymbolAddress(&p_cbs, g_cnt_bs);
    cudaGetSymbolAddress(&p_ibb, g_inv_bb); cudaGetSymbolAddress(&p_isb, g_inv_sb);
    cudaGetSymbolAddress(&p_ibs, g_inv_bs);
    cudaGetSymbolAddress(&p_Wb, g_Wb); cudaGetSymbolAddress(&p_Bb, g_Bb);
    cudaGetSymbolAddress(&p_Ws, g_Ws); cudaGetSymbolAddress(&p_Bs, g_Bs);

    float* xb_buf[2] = {(float*)p_xb0, (float*)p_xb1};
    float* xs_buf    = (float*)p_xs0;
    float* acc_bb = (float*)p_abb; float* acc_sb = (float*)p_asb; float* acc_bs = (float*)p_abs;
    float* cnt_bb = (float*)p_cbb; float* cnt_sb = (float*)p_csb; float* cnt_bs = (float*)p_cbs;
    float* inv_bb = (float*)p_ibb; float* inv_sb = (float*)p_isb; float* inv_bs = (float*)p_ibs;
    float* Wbp = (float*)p_Wb; float* Bbp = (float*)p_Bb;
    float* Wsp = (float*)p_Ws; float* Bsp = (float*)p_Bs;

    const int T = 256;

    // weight prep (tiny)
    prep_wb_kernel<<<(2 * 384 * 128 + T - 1) / T, T>>>(Wl, bl, Wr);
    prep_ws_kernel<<<(2 * 256 * 128 + T - 1) / T, T>>>(Wl, bl, Wr);

    // counts + inverse
    zero4_kernel<<<(NB_N / 4 + T - 1) / T, T>>>((float4*)cnt_bb, NB_N / 4);
    zero4_kernel<<<(NB_N / 4 + T - 1) / T, T>>>((float4*)cnt_sb, NB_N / 4);
    zero4_kernel<<<(NS_N / 4 + T - 1) / T, T>>>((float4*)cnt_bs, NS_N / 4);
    count_kernel<<<(E_BB_N + T - 1) / T, T>>>(ei_bb + E_BB_N, cnt_bb, E_BB_N);
    count_kernel<<<(E_SB_N + T - 1) / T, T>>>(ei_sb + E_SB_N, cnt_sb, E_SB_N);
    count_kernel<<<(E_BS_N + T - 1) / T, T>>>(ei_bs + E_BS_N, cnt_bs, E_BS_N);
    inv_kernel<<<(NB_N + T - 1) / T, T>>>(cnt_bb, inv_bb, NB_N);
    inv_kernel<<<(NB_N + T - 1) / T, T>>>(cnt_sb, inv_sb, NB_N);
    inv_kernel<<<(NS_N + T - 1) / T, T>>>(cnt_bs, inv_bs, NS_N);

    const int n4_b = NB_N * D_N / 4;   // 3.2M
    const int n4_s = NS_N * D_N / 4;   // 1.6M

    const float* cur_b = x_b;
    const float* cur_s = x_s;

    for (int l = 0; l < 2; ++l) {
        // zero accumulators
        zero4_kernel<<<(n4_b + T - 1) / T, T>>>((float4*)acc_bb, n4_b);
        zero4_kernel<<<(n4_b + T - 1) / T, T>>>((float4*)acc_sb, n4_b);
        if (l == 0)
            zero4_kernel<<<(n4_s + T - 1) / T, T>>>((float4*)acc_bs, n4_s);

        // scatter-sums (warp per edge)
        scatter_kernel<<<(E_BB_N * 32 + T - 1) / T, T>>>(cur_b, ei_bb, ei_bb + E_BB_N, acc_bb, E_BB_N);
        scatter_kernel<<<(E_SB_N * 32 + T - 1) / T, T>>>(cur_s, ei_sb, ei_sb + E_SB_N, acc_sb, E_SB_N);
        if (l == 0)
            scatter_kernel<<<(E_BS_N * 32 + T - 1) / T, T>>>(cur_b, ei_bs, ei_bs + E_BS_N, acc_bs, E_BS_N);

        // fused GEMM + bias + leaky_relu
        float* next_b = xb_buf[l];
        gemm_fused_kernel<<<(NB_N + 127) / 128, 256>>>(
            acc_bb, acc_sb, cur_b, inv_bb, inv_sb, nullptr,
            Wbp + (size_t)l * 384 * 128, Bbp + (size_t)l * 128,
            next_b, NB_N, 3);
        if (l == 0) {
            // layer-2 x_s update is dead code (never reaches the output) — only layer-1
            gemm_fused_kernel<<<(NS_N + 127) / 128, 256>>>(
                acc_bs, cur_s, nullptr, inv_bs, nullptr, nullptr,
                Wsp, Bsp,
                xs_buf, NS_N, 2);
            cur_s = xs_buf;
        }
        cur_b = next_b;
    }

    // readout heads
    head_kernel<<<(NB_N + 7) / 8, 256>>>(cur_b, Wh, bh, (float*)d_out);
}

// round 5
// speedup vs baseline: 1.3144x; 1.3144x over previous
#include <cuda_runtime.h>
#include <cuda_bf16.h>
#include <cstdint>
#include <cstddef>

// ---------------- problem constants ----------------
#define NB_N   100000
#define NS_N   50000
#define D_N    128
#define NHEADS 8
#define E_BB_N 800000
#define E_SB_N 400000
#define E_BS_N 400000

// ---------------- device scratch (static; no allocation) ----------------
__device__ float g_xb0[(size_t)NB_N * D_N];
__device__ float g_xb1[(size_t)NB_N * D_N];
__device__ float g_xs0[(size_t)NS_N * D_N];

__device__ float g_acc_bb[(size_t)NB_N * D_N];
__device__ float g_acc_sb[(size_t)NB_N * D_N];
__device__ float g_acc_bs[(size_t)NS_N * D_N];

__device__ float g_cnt_bb[NB_N];
__device__ float g_cnt_sb[NB_N];
__device__ float g_cnt_bs[NS_N];
__device__ float g_inv_bb[NB_N];
__device__ float g_inv_sb[NB_N];
__device__ float g_inv_bs[NS_N];

// combined fp32 weights: b-dst [2][384][128] (k-major), s-dst layer0 [256][128]
__device__ float g_Wb[2][384 * 128];
__device__ float g_Bb[2][128];
__device__ float g_Ws[256 * 128];
__device__ float g_Bs[128];

// B in HMMA fragment order: per (ktile, ntile, lane) a uint4 {hi_b0, hi_b1, lo_b0, lo_b1}
__device__ uint4 g_WfragB[2 * 24 * 16 * 32];   // 2 layers, K=384 -> 24 k16-tiles, N=128 -> 16 n8-tiles
__device__ uint4 g_WfragS[16 * 16 * 32];       // layer-0 s: K=256 -> 16 k16-tiles

// ---------------- split-bf16 pack: hi = truncate-to-bf16, lo = RN(residual) ----------------
__device__ __forceinline__ void split_pack(float v0, float v1, uint32_t& hp, uint32_t& lp) {
    uint32_t b0 = __float_as_uint(v0), b1 = __float_as_uint(v1);
    hp = (b1 & 0xFFFF0000u) | (b0 >> 16);
    float h0 = __uint_as_float(b0 & 0xFFFF0000u);
    float h1 = __uint_as_float(b1 & 0xFFFF0000u);
    // cvt.rn.bf16x2.f32 d, a, b  -> d = {a(hi16), b(lo16)}
    asm("cvt.rn.bf16x2.f32 %0, %1, %2;" : "=r"(lp) : "f"(v1 - h1), "f"(v0 - h0));
}

__device__ __forceinline__ void mma_bf16(float* c, const uint32_t* a, uint32_t b0, uint32_t b1) {
    asm volatile("mma.sync.aligned.m16n8k16.row.col.f32.bf16.bf16.f32 "
                 "{%0,%1,%2,%3}, {%4,%5,%6,%7}, {%8,%9}, {%0,%1,%2,%3};"
                 : "+f"(c[0]), "+f"(c[1]), "+f"(c[2]), "+f"(c[3])
                 : "r"(a[0]), "r"(a[1]), "r"(a[2]), "r"(a[3]), "r"(b0), "r"(b1));
}

// ---------------- small helpers ----------------
__global__ void zero4_kernel(float4* __restrict__ p, int n4) {
    int i = blockIdx.x * blockDim.x + threadIdx.x;
    if (i < n4) p[i] = make_float4(0.f, 0.f, 0.f, 0.f);
}
__global__ void count_kernel(const int* __restrict__ dst, float* __restrict__ cnt, int E) {
    int e = blockIdx.x * blockDim.x + threadIdx.x;
    if (e < E) atomicAdd(cnt + dst[e], 1.0f);
}
__global__ void inv_kernel(const float* __restrict__ cnt, float* __restrict__ inv, int n) {
    int i = blockIdx.x * blockDim.x + threadIdx.x;
    if (i < n) inv[i] = 1.0f / fmaxf(cnt[i], 1.0f);
}

// one warp per edge: gather 128 floats from x[src], vectored red.add into acc[dst]
__global__ void scatter_kernel(const float* __restrict__ x,
                               const int* __restrict__ src,
                               const int* __restrict__ dst,
                               float* __restrict__ acc, int E) {
    int w    = (blockIdx.x * blockDim.x + threadIdx.x) >> 5;
    int lane = threadIdx.x & 31;
    if (w >= E) return;
    int s = src[w];
    int d = dst[w];
    float4 v = reinterpret_cast<const float4*>(x + (size_t)s * D_N)[lane];
    float* p = acc + (size_t)d * D_N + lane * 4;
    asm volatile("red.global.add.v4.f32 [%0], {%1, %2, %3, %4};"
                 :: "l"(p), "f"(v.x), "f"(v.y), "f"(v.z), "f"(v.w) : "memory");
}

// ---------------- weight prep ----------------
__global__ void prep_wb_kernel(const float* __restrict__ Wl, const float* __restrict__ bl,
                               const float* __restrict__ Wr) {
    int idx = blockIdx.x * blockDim.x + threadIdx.x;
    const int total = 2 * 384 * 128;
    if (idx < total) {
        int l = idx / (384 * 128);
        int r = idx % (384 * 128);
        int k = r / 128, n = r % 128;
        float v;
        if (k < 128)      v = Wl[((size_t)(l * 3 + 0) * 128 + k) * 128 + n];
        else if (k < 256) v = Wl[((size_t)(l * 3 + 1) * 128 + (k - 128)) * 128 + n];
        else              v = Wr[((size_t)(l * 3 + 0) * 128 + (k - 256)) * 128 + n]
                            + Wr[((size_t)(l * 3 + 1) * 128 + (k - 256)) * 128 + n];
        g_Wb[l][r] = v;
    }
    if (idx < 2 * 128) {
        int l = idx / 128, n = idx % 128;
        g_Bb[l][n] = bl[(l * 3 + 0) * 128 + n] + bl[(l * 3 + 1) * 128 + n];
    }
}
__global__ void prep_ws_kernel(const float* __restrict__ Wl, const float* __restrict__ bl,
                               const float* __restrict__ Wr) {
    int idx = blockIdx.x * blockDim.x + threadIdx.x;
    const int total = 256 * 128;
    if (idx < total) {
        int k = idx / 128, n = idx % 128;
        float v;
        if (k < 128) v = Wl[((size_t)2 * 128 + k) * 128 + n];
        else         v = Wr[((size_t)2 * 128 + (k - 128)) * 128 + n];
        g_Ws[idx] = v;
    }
    if (idx < 128) g_Bs[idx] = bl[2 * 128 + idx];
}

// pack combined weights into HMMA B-fragment order (hi/lo split)
__global__ void prep_bfrag_b_kernel() {
    int idx = blockIdx.x * blockDim.x + threadIdx.x;   // 2*24*16*32 = 24576
    if (idx >= 2 * 24 * 16 * 32) return;
    int lane = idx & 31;
    int nt   = (idx >> 5) & 15;
    int t    = idx >> 9;
    int kt   = t % 24;
    int l    = t / 24;
    int n  = nt * 8 + (lane >> 2);
    int k0 = kt * 16 + (lane & 3) * 2;
    const float* W = g_Wb[l];
    float v0 = W[(k0 + 0) * 128 + n], v1 = W[(k0 + 1) * 128 + n];
    float v8 = W[(k0 + 8) * 128 + n], v9 = W[(k0 + 9) * 128 + n];
    uint32_t h0, l0, h1, l1;
    split_pack(v0, v1, h0, l0);
    split_pack(v8, v9, h1, l1);
    g_WfragB[idx] = make_uint4(h0, h1, l0, l1);
}
__global__ void prep_bfrag_s_kernel() {
    int idx = blockIdx.x * blockDim.x + threadIdx.x;   // 16*16*32 = 8192
    if (idx >= 16 * 16 * 32) return;
    int lane = idx & 31;
    int nt   = (idx >> 5) & 15;
    int kt   = idx >> 9;
    int n  = nt * 8 + (lane >> 2);
    int k0 = kt * 16 + (lane & 3) * 2;
    float v0 = g_Ws[(k0 + 0) * 128 + n], v1 = g_Ws[(k0 + 1) * 128 + n];
    float v8 = g_Ws[(k0 + 8) * 128 + n], v9 = g_Ws[(k0 + 9) * 128 + n];
    uint32_t h0, l0, h1, l1;
    split_pack(v0, v1, h0, l0);
    split_pack(v8, v9, h1, l1);
    g_WfragS[idx] = make_uint4(h0, h1, l0, l1);
}

// ---------------- HMMA fused segmented GEMM + bias + leaky_relu ----------------
// out[M,128] = leaky( [A0*s0 | A1*s1 | (A2*s2)] @ Wcomb + bias )
// block: 128 rows x 128 cols, 8 warps in 4(M) x 2(N); warp tile 32x64.
// split-bf16 3-MMA scheme: D += Ah*Bh + Al*Bh + Ah*Bl (fp32 accum).

__device__ __forceinline__ void load_rawA(const float* __restrict__ A0,
                                          const float* __restrict__ A1,
                                          const float* __restrict__ A2,
                                          int kt, int row_lo, int lc, int M,
                                          float2 (&xa)[2][2], float2 (&xb)[2][2]) {
    const int seg = kt >> 3;
    const int kk  = (kt & 7) * 16;
    const float* A = (seg == 0) ? A0 : ((seg == 1) ? A1 : A2);
    #pragma unroll
    for (int mt = 0; mt < 2; ++mt)
        #pragma unroll
        for (int half = 0; half < 2; ++half) {
            int r = row_lo + mt * 16 + half * 8;
            float2 v0 = make_float2(0.f, 0.f), v1 = v0;
            if (r < M) {
                const float* p = A + (size_t)r * D_N + kk + lc;
                v0 = *reinterpret_cast<const float2*>(p);
                v1 = *reinterpret_cast<const float2*>(p + 8);
            }
            xa[mt][half] = v0;
            xb[mt][half] = v1;
        }
}

__global__ void __launch_bounds__(256)
gemm_mma_kernel(const float* __restrict__ A0, const float* __restrict__ A1,
                const float* __restrict__ A2,
                const float* __restrict__ s0, const float* __restrict__ s1,
                const float* __restrict__ s2,
                const uint4* __restrict__ Bfrag, const float* __restrict__ bias,
                float* __restrict__ out, int M, int nseg) {
    __shared__ float scl[3][128];
    __shared__ float bsh[128];

    const int tid    = threadIdx.x;
    const int lane   = tid & 31;
    const int wid    = tid >> 5;
    const int warp_m = wid & 3;
    const int warp_n = wid >> 2;
    const int row0   = blockIdx.x * 128;

    if (tid < 128) {
        int r = row0 + tid;
        bool ok = r < M;
        scl[0][tid] = (s0 && ok) ? s0[r] : 1.0f;
        scl[1][tid] = (s1 && ok) ? s1[r] : 1.0f;
        scl[2][tid] = (s2 && ok) ? s2[r] : 1.0f;
        bsh[tid] = bias[tid];
    }
    __syncthreads();

    const int lr  = lane >> 2;           // 0..7
    const int lc  = (lane & 3) * 2;      // 0,2,4,6
    const int mrl = warp_m * 32 + lr;    // row-in-block base (add mt*16, half*8)
    const int row_lo = row0 + mrl;

    float c[2][8][4] = {};

    const int K16 = nseg * 8;

    float2 ra[2][2], rb[2][2], na[2][2], nb[2][2];
    load_rawA(A0, A1, A2, 0, row_lo, lc, M, ra, rb);

    for (int kt = 0; kt < K16; ++kt) {
        if (kt + 1 < K16)
            load_rawA(A0, A1, A2, kt + 1, row_lo, lc, M, na, nb);

        const int seg = kt >> 3;
        uint32_t ah[2][4], al[2][4];
        #pragma unroll
        for (int mt = 0; mt < 2; ++mt)
            #pragma unroll
            for (int half = 0; half < 2; ++half) {
                float sc = scl[seg][mrl + mt * 16 + half * 8];
                split_pack(ra[mt][half].x * sc, ra[mt][half].y * sc,
                           ah[mt][half], al[mt][half]);
                split_pack(rb[mt][half].x * sc, rb[mt][half].y * sc,
                           ah[mt][2 + half], al[mt][2 + half]);
            }

        const uint4* bp = Bfrag + ((size_t)kt * 16 + warp_n * 8) * 32 + lane;
        #pragma unroll
        for (int nt = 0; nt < 8; ++nt) {
            uint4 b = bp[nt * 32];
            #pragma unroll
            for (int mt = 0; mt < 2; ++mt) {
                mma_bf16(c[mt][nt], ah[mt], b.x, b.y);   // Ah*Bh
                mma_bf16(c[mt][nt], al[mt], b.x, b.y);   // Al*Bh
                mma_bf16(c[mt][nt], ah[mt], b.z, b.w);   // Ah*Bl
            }
        }

        #pragma unroll
        for (int mt = 0; mt < 2; ++mt)
            #pragma unroll
            for (int half = 0; half < 2; ++half) {
                ra[mt][half] = na[mt][half];
                rb[mt][half] = nb[mt][half];
            }
    }

    // ---- epilogue: bias + leaky_relu ----
    #pragma unroll
    for (int mt = 0; mt < 2; ++mt) {
        #pragma unroll
        for (int nt = 0; nt < 8; ++nt) {
            int col = warp_n * 64 + nt * 8 + lc;
            float b0 = bsh[col], b1 = bsh[col + 1];
            int r0 = row_lo + mt * 16;
            int r1 = r0 + 8;
            if (r0 < M) {
                float2 o;
                o.x = c[mt][nt][0] + b0; o.x = o.x > 0.f ? o.x : 0.01f * o.x;
                o.y = c[mt][nt][1] + b1; o.y = o.y > 0.f ? o.y : 0.01f * o.y;
                *reinterpret_cast<float2*>(out + (size_t)r0 * D_N + col) = o;
            }
            if (r1 < M) {
                float2 o;
                o.x = c[mt][nt][2] + b0; o.x = o.x > 0.f ? o.x : 0.01f * o.x;
                o.y = c[mt][nt][3] + b1; o.y = o.y > 0.f ? o.y : 0.01f * o.y;
                *reinterpret_cast<float2*>(out + (size_t)r1 * D_N + col) = o;
            }
        }
    }
}

// ---------------- classification head ----------------
__global__ void head_kernel(const float* __restrict__ x, const float* __restrict__ Wh,
                            const float* __restrict__ bh, float* __restrict__ out) {
    __shared__ float wsh[NHEADS][128];
    __shared__ float bsh[NHEADS];
    int tid = threadIdx.x;
    for (int i = tid; i < NHEADS * 128; i += blockDim.x) wsh[i >> 7][i & 127] = Wh[i];
    if (tid < NHEADS) bsh[tid] = bh[tid];
    __syncthreads();

    int node = blockIdx.x * (blockDim.x >> 5) + (tid >> 5);
    int lane = tid & 31;
    if (node >= NB_N) return;
    float4 xv = *reinterpret_cast<const float4*>(x + (size_t)node * 128 + lane * 4);
    #pragma unroll
    for (int h = 0; h < NHEADS; ++h) {
        float4 wv = *reinterpret_cast<const float4*>(&wsh[h][lane * 4]);
        float p = xv.x * wv.x + xv.y * wv.y + xv.z * wv.z + xv.w * wv.w;
        #pragma unroll
        for (int o = 16; o > 0; o >>= 1) p += __shfl_down_sync(0xffffffffu, p, o);
        if (lane == 0) out[(size_t)node * NHEADS + h] = p + bsh[h];
    }
}

// ---------------- host launch ----------------
extern "C" void kernel_launch(void* const* d_in, const int* in_sizes, int n_in,
                              void* d_out, int out_size) {
    (void)in_sizes; (void)n_in; (void)out_size;
    const float* x_b  = (const float*)d_in[0];
    const float* x_s  = (const float*)d_in[1];
    const float* Wl   = (const float*)d_in[2];
    const float* bl   = (const float*)d_in[3];
    const float* Wr   = (const float*)d_in[4];
    const float* Wh   = (const float*)d_in[5];
    const float* bh   = (const float*)d_in[6];
    const int*   ei_bb = (const int*)d_in[7];   // JAX x64 off -> int32 indices
    const int*   ei_sb = (const int*)d_in[8];
    const int*   ei_bs = (const int*)d_in[9];

    void *p_xb0, *p_xb1, *p_xs0, *p_abb, *p_asb, *p_abs;
    void *p_cbb, *p_csb, *p_cbs, *p_ibb, *p_isb, *p_ibs;
    void *p_Bb, *p_Bs, *p_FB, *p_FS;
    cudaGetSymbolAddress(&p_xb0, g_xb0);  cudaGetSymbolAddress(&p_xb1, g_xb1);
    cudaGetSymbolAddress(&p_xs0, g_xs0);
    cudaGetSymbolAddress(&p_abb, g_acc_bb); cudaGetSymbolAddress(&p_asb, g_acc_sb);
    cudaGetSymbolAddress(&p_abs, g_acc_bs);
    cudaGetSymbolAddress(&p_cbb, g_cnt_bb); cudaGetSymbolAddress(&p_csb, g_cnt_sb);
    cudaGetSymbolAddress(&p_cbs, g_cnt_bs);
    cudaGetSymbolAddress(&p_ibb, g_inv_bb); cudaGetSymbolAddress(&p_isb, g_inv_sb);
    cudaGetSymbolAddress(&p_ibs, g_inv_bs);
    cudaGetSymbolAddress(&p_Bb, g_Bb); cudaGetSymbolAddress(&p_Bs, g_Bs);
    cudaGetSymbolAddress(&p_FB, g_WfragB); cudaGetSymbolAddress(&p_FS, g_WfragS);

    float* xb_buf[2] = {(float*)p_xb0, (float*)p_xb1};
    float* xs_buf    = (float*)p_xs0;
    float* acc_bb = (float*)p_abb; float* acc_sb = (float*)p_asb; float* acc_bs = (float*)p_abs;
    float* cnt_bb = (float*)p_cbb; float* cnt_sb = (float*)p_csb; float* cnt_bs = (float*)p_cbs;
    float* inv_bb = (float*)p_ibb; float* inv_sb = (float*)p_isb; float* inv_bs = (float*)p_ibs;
    float* Bbp = (float*)p_Bb; float* Bsp = (float*)p_Bs;
    const uint4* FragB = (const uint4*)p_FB;
    const uint4* FragS = (const uint4*)p_FS;

    const int T = 256;

    // weight prep (fp32 combine, then HMMA fragment packing)
    prep_wb_kernel<<<(2 * 384 * 128 + T - 1) / T, T>>>(Wl, bl, Wr);
    prep_ws_kernel<<<(256 * 128 + T - 1) / T, T>>>(Wl, bl, Wr);
    prep_bfrag_b_kernel<<<(2 * 24 * 16 * 32 + T - 1) / T, T>>>();
    prep_bfrag_s_kernel<<<(16 * 16 * 32 + T - 1) / T, T>>>();

    // counts + inverse
    zero4_kernel<<<(NB_N / 4 + T - 1) / T, T>>>((float4*)cnt_bb, NB_N / 4);
    zero4_kernel<<<(NB_N / 4 + T - 1) / T, T>>>((float4*)cnt_sb, NB_N / 4);
    zero4_kernel<<<(NS_N / 4 + T - 1) / T, T>>>((float4*)cnt_bs, NS_N / 4);
    count_kernel<<<(E_BB_N + T - 1) / T, T>>>(ei_bb + E_BB_N, cnt_bb, E_BB_N);
    count_kernel<<<(E_SB_N + T - 1) / T, T>>>(ei_sb + E_SB_N, cnt_sb, E_SB_N);
    count_kernel<<<(E_BS_N + T - 1) / T, T>>>(ei_bs + E_BS_N, cnt_bs, E_BS_N);
    inv_kernel<<<(NB_N + T - 1) / T, T>>>(cnt_bb, inv_bb, NB_N);
    inv_kernel<<<(NB_N + T - 1) / T, T>>>(cnt_sb, inv_sb, NB_N);
    inv_kernel<<<(NS_N + T - 1) / T, T>>>(cnt_bs, inv_bs, NS_N);

    const int n4_b = NB_N * D_N / 4;
    const int n4_s = NS_N * D_N / 4;

    const float* cur_b = x_b;
    const float* cur_s = x_s;

    for (int l = 0; l < 2; ++l) {
        zero4_kernel<<<(n4_b + T - 1) / T, T>>>((float4*)acc_bb, n4_b);
        zero4_kernel<<<(n4_b + T - 1) / T, T>>>((float4*)acc_sb, n4_b);
        if (l == 0)
            zero4_kernel<<<(n4_s + T - 1) / T, T>>>((float4*)acc_bs, n4_s);

        scatter_kernel<<<(E_BB_N * 32 + T - 1) / T, T>>>(cur_b, ei_bb, ei_bb + E_BB_N, acc_bb, E_BB_N);
        scatter_kernel<<<(E_SB_N * 32 + T - 1) / T, T>>>(cur_s, ei_sb, ei_sb + E_SB_N, acc_sb, E_SB_N);
        if (l == 0)
            scatter_kernel<<<(E_BS_N * 32 + T - 1) / T, T>>>(cur_b, ei_bs, ei_bs + E_BS_N, acc_bs, E_BS_N);

        float* next_b = xb_buf[l];
        gemm_mma_kernel<<<(NB_N + 127) / 128, 256>>>(
            acc_bb, acc_sb, cur_b, inv_bb, inv_sb, nullptr,
            FragB + (size_t)l * 24 * 16 * 32, Bbp + (size_t)l * 128,
            next_b, NB_N, 3);
        if (l == 0) {
            // layer-2 x_s update is dead code (never reaches output) — only layer-1
            gemm_mma_kernel<<<(NS_N + 127) / 128, 256>>>(
                acc_bs, cur_s, nullptr, inv_bs, nullptr, nullptr,
                FragS, Bsp,
                xs_buf, NS_N, 2);
            cur_s = xs_buf;
        }
        cur_b = next_b;
    }

    head_kernel<<<(NB_N + 7) / 8, 256>>>(cur_b, Wh, bh, (float*)d_out);
}

// round 7
// speedup vs baseline: 1.6565x; 1.2603x over previous
#include <cuda_runtime.h>
#include <cuda_bf16.h>
#include <cstdint>
#include <cstddef>

// ---------------- problem constants ----------------
#define NB_N   100000
#define NS_N   50000
#define D_N    128
#define NHEADS 8
#define E_BB_N 800000
#define E_SB_N 400000
#define E_BS_N 400000

// ---------------- device scratch (static; no allocation) ----------------
__device__ float g_xb0[(size_t)NB_N * D_N];
__device__ float g_xb1[(size_t)NB_N * D_N];
__device__ float g_xs0[(size_t)NS_N * D_N];

__device__ float g_acc_bb[(size_t)NB_N * D_N];   // holds per-dst MEAN after segmean
__device__ float g_acc_sb[(size_t)NB_N * D_N];
__device__ float g_acc_bs[(size_t)NS_N * D_N];

// CSR structures per edge type
__device__ int g_cnti_bb[NB_N];
__device__ int g_off_bb[NB_N];
__device__ int g_cur_bb[NB_N];
__device__ int g_perm_bb[E_BB_N];
__device__ int g_cnti_sb[NB_N];
__device__ int g_off_sb[NB_N];
__device__ int g_cur_sb[NB_N];
__device__ int g_perm_sb[E_SB_N];
__device__ int g_cnti_bs[NS_N];
__device__ int g_off_bs[NS_N];
__device__ int g_cur_bs[NS_N];
__device__ int g_perm_bs[E_BS_N];

// dedicated scan-partial buffers (MUST NOT alias cur - r6 bug)
__device__ int g_part_bb[128];
__device__ int g_part_sb[128];
__device__ int g_part_bs[128];

// combined fp32 weights: b-dst [2][384][128] (k-major), s-dst layer0 [256][128]
__device__ float g_Wb[2][384 * 128];
__device__ float g_Bb[2][128];
__device__ float g_Ws[256 * 128];
__device__ float g_Bs[128];

// B in HMMA fragment order: per (ktile, ntile, lane) a uint4 {hi_b0, hi_b1, lo_b0, lo_b1}
__device__ uint4 g_WfragB[2 * 24 * 16 * 32];
__device__ uint4 g_WfragS[16 * 16 * 32];

// ---------------- split-bf16 pack: hi = truncate-to-bf16, lo = RN(residual) ----------------
__device__ __forceinline__ void split_pack(float v0, float v1, uint32_t& hp, uint32_t& lp) {
    uint32_t b0 = __float_as_uint(v0), b1 = __float_as_uint(v1);
    hp = (b1 & 0xFFFF0000u) | (b0 >> 16);
    float h0 = __uint_as_float(b0 & 0xFFFF0000u);
    float h1 = __uint_as_float(b1 & 0xFFFF0000u);
    asm("cvt.rn.bf16x2.f32 %0, %1, %2;" : "=r"(lp) : "f"(v1 - h1), "f"(v0 - h0));
}

__device__ __forceinline__ void mma_bf16(float* c, const uint32_t* a, uint32_t b0, uint32_t b1) {
    asm volatile("mma.sync.aligned.m16n8k16.row.col.f32.bf16.bf16.f32 "
                 "{%0,%1,%2,%3}, {%4,%5,%6,%7}, {%8,%9}, {%0,%1,%2,%3};"
                 : "+f"(c[0]), "+f"(c[1]), "+f"(c[2]), "+f"(c[3])
                 : "r"(a[0]), "r"(a[1]), "r"(a[2]), "r"(a[3]), "r"(b0), "r"(b1));
}

// ---------------- CSR build kernels ----------------
__global__ void zeroi_kernel(int4* __restrict__ p, int n4) {
    int i = blockIdx.x * blockDim.x + threadIdx.x;
    if (i < n4) p[i] = make_int4(0, 0, 0, 0);
}
__global__ void counti_kernel(const int* __restrict__ dst, int* __restrict__ cnt, int E) {
    int e = blockIdx.x * blockDim.x + threadIdx.x;
    if (e < E) atomicAdd(cnt + dst[e], 1);
}

#define SCHUNK 1024
// phase A: per-1024-chunk sums
__global__ void scanA_kernel(const int* __restrict__ cnt, int* __restrict__ part, int n) {
    __shared__ int sh[SCHUNK];
    int t = threadIdx.x;
    int i = blockIdx.x * SCHUNK + t;
    sh[t] = (i < n) ? cnt[i] : 0;
    __syncthreads();
    #pragma unroll
    for (int s = 512; s > 0; s >>= 1) {
        if (t < s) sh[t] += sh[t + s];
        __syncthreads();
    }
    if (t == 0) part[blockIdx.x] = sh[0];
}
// phase B: single-block exclusive scan of partials (nb <= 128)
__global__ void scanB_kernel(int* __restrict__ part, int nb) {
    __shared__ int sh[128];
    int t = threadIdx.x;
    int v = (t < nb) ? part[t] : 0;
    sh[t] = v;
    __syncthreads();
    #pragma unroll
    for (int s = 1; s < 128; s <<= 1) {
        int a = (t >= s) ? sh[t - s] : 0;
        __syncthreads();
        sh[t] += a;
        __syncthreads();
    }
    if (t < nb) part[t] = sh[t] - v;
}
// phase C: per-chunk exclusive scan + partial offset -> off, cursor
__global__ void scanC_kernel(const int* __restrict__ cnt, const int* __restrict__ part,
                             int* __restrict__ off, int* __restrict__ cur, int n) {
    __shared__ int sh[SCHUNK];
    int t = threadIdx.x;
    int i = blockIdx.x * SCHUNK + t;
    int v = (i < n) ? cnt[i] : 0;
    sh[t] = v;
    __syncthreads();
    #pragma unroll
    for (int s = 1; s < SCHUNK; s <<= 1) {
        int a = (t >= s) ? sh[t - s] : 0;
        __syncthreads();
        sh[t] += a;
        __syncthreads();
    }
    if (i < n) {
        int ex = sh[t] - v + part[blockIdx.x];
        off[i] = ex;
        cur[i] = ex;
    }
}
__global__ void fill_kernel(const int* __restrict__ src, const int* __restrict__ dst,
                            int* __restrict__ cur, int* __restrict__ perm, int E) {
    int e = blockIdx.x * blockDim.x + threadIdx.x;
    if (e < E) {
        int p = atomicAdd(cur + dst[e], 1);
        perm[p] = src[e];
    }
}

// ---------------- segmented mean: one warp per dst node ----------------
__global__ void __launch_bounds__(256)
segmean_kernel(const float* __restrict__ x, const int* __restrict__ perm,
               const int* __restrict__ off, const int* __restrict__ cnti,
               float* __restrict__ out, int n) {
    int w    = (blockIdx.x * blockDim.x + threadIdx.x) >> 5;
    int lane = threadIdx.x & 31;
    if (w >= n) return;
    int o = off[w];
    int c = cnti[w];
    float4 acc = make_float4(0.f, 0.f, 0.f, 0.f);
    int i = 0;
    for (; i + 4 <= c; i += 4) {
        int s0 = perm[o + i], s1 = perm[o + i + 1], s2 = perm[o + i + 2], s3 = perm[o + i + 3];
        float4 v0 = reinterpret_cast<const float4*>(x + (size_t)s0 * D_N)[lane];
        float4 v1 = reinterpret_cast<const float4*>(x + (size_t)s1 * D_N)[lane];
        float4 v2 = reinterpret_cast<const float4*>(x + (size_t)s2 * D_N)[lane];
        float4 v3 = reinterpret_cast<const float4*>(x + (size_t)s3 * D_N)[lane];
        acc.x += v0.x + v1.x + v2.x + v3.x;
        acc.y += v0.y + v1.y + v2.y + v3.y;
        acc.z += v0.z + v1.z + v2.z + v3.z;
        acc.w += v0.w + v1.w + v2.w + v3.w;
    }
    for (; i < c; ++i) {
        int s = perm[o + i];
        float4 v = reinterpret_cast<const float4*>(x + (size_t)s * D_N)[lane];
        acc.x += v.x; acc.y += v.y; acc.z += v.z; acc.w += v.w;
    }
    float inv = (c > 0) ? 1.0f / (float)c : 0.0f;
    acc.x *= inv; acc.y *= inv; acc.z *= inv; acc.w *= inv;
    reinterpret_cast<float4*>(out + (size_t)w * D_N)[lane] = acc;
}

// ---------------- weight prep ----------------
__global__ void prep_wb_kernel(const float* __restrict__ Wl, const float* __restrict__ bl,
                               const float* __restrict__ Wr) {
    int idx = blockIdx.x * blockDim.x + threadIdx.x;
    const int total = 2 * 384 * 128;
    if (idx < total) {
        int l = idx / (384 * 128);
        int r = idx % (384 * 128);
        int k = r / 128, n = r % 128;
        float v;
        if (k < 128)      v = Wl[((size_t)(l * 3 + 0) * 128 + k) * 128 + n];
        else if (k < 256) v = Wl[((size_t)(l * 3 + 1) * 128 + (k - 128)) * 128 + n];
        else              v = Wr[((size_t)(l * 3 + 0) * 128 + (k - 256)) * 128 + n]
                            + Wr[((size_t)(l * 3 + 1) * 128 + (k - 256)) * 128 + n];
        g_Wb[l][r] = v;
    }
    if (idx < 2 * 128) {
        int l = idx / 128, n = idx % 128;
        g_Bb[l][n] = bl[(l * 3 + 0) * 128 + n] + bl[(l * 3 + 1) * 128 + n];
    }
}
__global__ void prep_ws_kernel(const float* __restrict__ Wl, const float* __restrict__ bl,
                               const float* __restrict__ Wr) {
    int idx = blockIdx.x * blockDim.x + threadIdx.x;
    const int total = 256 * 128;
    if (idx < total) {
        int k = idx / 128, n = idx % 128;
        float v;
        if (k < 128) v = Wl[((size_t)2 * 128 + k) * 128 + n];
        else         v = Wr[((size_t)2 * 128 + (k - 128)) * 128 + n];
        g_Ws[idx] = v;
    }
    if (idx < 128) g_Bs[idx] = bl[2 * 128 + idx];
}
__global__ void prep_bfrag_b_kernel() {
    int idx = blockIdx.x * blockDim.x + threadIdx.x;
    if (idx >= 2 * 24 * 16 * 32) return;
    int lane = idx & 31;
    int nt   = (idx >> 5) & 15;
    int t    = idx >> 9;
    int kt   = t % 24;
    int l    = t / 24;
    int n  = nt * 8 + (lane >> 2);
    int k0 = kt * 16 + (lane & 3) * 2;
    const float* W = g_Wb[l];
    float v0 = W[(k0 + 0) * 128 + n], v1 = W[(k0 + 1) * 128 + n];
    float v8 = W[(k0 + 8) * 128 + n], v9 = W[(k0 + 9) * 128 + n];
    uint32_t h0, l0, h1, l1;
    split_pack(v0, v1, h0, l0);
    split_pack(v8, v9, h1, l1);
    g_WfragB[idx] = make_uint4(h0, h1, l0, l1);
}
__global__ void prep_bfrag_s_kernel() {
    int idx = blockIdx.x * blockDim.x + threadIdx.x;
    if (idx >= 16 * 16 * 32) return;
    int lane = idx & 31;
    int nt   = (idx >> 5) & 15;
    int kt   = idx >> 9;
    int n  = nt * 8 + (lane >> 2);
    int k0 = kt * 16 + (lane & 3) * 2;
    float v0 = g_Ws[(k0 + 0) * 128 + n], v1 = g_Ws[(k0 + 1) * 128 + n];
    float v8 = g_Ws[(k0 + 8) * 128 + n], v9 = g_Ws[(k0 + 9) * 128 + n];
    uint32_t h0, l0, h1, l1;
    split_pack(v0, v1, h0, l0);
    split_pack(v8, v9, h1, l1);
    g_WfragS[idx] = make_uint4(h0, h1, l0, l1);
}

// ---------------- HMMA fused segmented GEMM + bias + leaky_relu ----------------
// out[M,128] = leaky( [A0 | A1 | (A2)] @ Wcomb + bias )   (A segments pre-normalized)
__device__ __forceinline__ void load_rawA(const float* __restrict__ A0,
                                          const float* __restrict__ A1,
                                          const float* __restrict__ A2,
                                          int kt, int row_lo, int lc, int M,
                                          float2 (&xa)[2][2], float2 (&xb)[2][2]) {
    const int seg = kt >> 3;
    const int kk  = (kt & 7) * 16;
    const float* A = (seg == 0) ? A0 : ((seg == 1) ? A1 : A2);
    #pragma unroll
    for (int mt = 0; mt < 2; ++mt)
        #pragma unroll
        for (int half = 0; half < 2; ++half) {
            int r = row_lo + mt * 16 + half * 8;
            float2 v0 = make_float2(0.f, 0.f), v1 = v0;
            if (r < M) {
                const float* p = A + (size_t)r * D_N + kk + lc;
                v0 = *reinterpret_cast<const float2*>(p);
                v1 = *reinterpret_cast<const float2*>(p + 8);
            }
            xa[mt][half] = v0;
            xb[mt][half] = v1;
        }
}

__global__ void __launch_bounds__(256)
gemm_mma_kernel(const float* __restrict__ A0, const float* __restrict__ A1,
                const float* __restrict__ A2,
                const uint4* __restrict__ Bfrag, const float* __restrict__ bias,
                float* __restrict__ out, int M, int nseg) {
    __shared__ float bsh[128];

    const int tid    = threadIdx.x;
    const int lane   = tid & 31;
    const int wid    = tid >> 5;
    const int warp_m = wid & 3;
    const int warp_n = wid >> 2;
    const int row0   = blockIdx.x * 128;

    if (tid < 128) bsh[tid] = bias[tid];
    __syncthreads();

    const int lr  = lane >> 2;
    const int lc  = (lane & 3) * 2;
    const int mrl = warp_m * 32 + lr;
    const int row_lo = row0 + mrl;

    float c[2][8][4] = {};
    const int K16 = nseg * 8;

    float2 ra[2][2], rb[2][2], na[2][2], nb[2][2];
    load_rawA(A0, A1, A2, 0, row_lo, lc, M, ra, rb);

    for (int kt = 0; kt < K16; ++kt) {
        if (kt + 1 < K16)
            load_rawA(A0, A1, A2, kt + 1, row_lo, lc, M, na, nb);

        uint32_t ah[2][4], al[2][4];
        #pragma unroll
        for (int mt = 0; mt < 2; ++mt)
            #pragma unroll
            for (int half = 0; half < 2; ++half) {
                split_pack(ra[mt][half].x, ra[mt][half].y, ah[mt][half], al[mt][half]);
                split_pack(rb[mt][half].x, rb[mt][half].y, ah[mt][2 + half], al[mt][2 + half]);
            }

        const uint4* bp = Bfrag + ((size_t)kt * 16 + warp_n * 8) * 32 + lane;
        #pragma unroll
        for (int nt = 0; nt < 8; ++nt) {
            uint4 b = bp[nt * 32];
            #pragma unroll
            for (int mt = 0; mt < 2; ++mt) {
                mma_bf16(c[mt][nt], ah[mt], b.x, b.y);
                mma_bf16(c[mt][nt], al[mt], b.x, b.y);
                mma_bf16(c[mt][nt], ah[mt], b.z, b.w);
            }
        }

        #pragma unroll
        for (int mt = 0; mt < 2; ++mt)
            #pragma unroll
            for (int half = 0; half < 2; ++half) {
                ra[mt][half] = na[mt][half];
                rb[mt][half] = nb[mt][half];
            }
    }

    #pragma unroll
    for (int mt = 0; mt < 2; ++mt) {
        #pragma unroll
        for (int nt = 0; nt < 8; ++nt) {
            int col = warp_n * 64 + nt * 8 + lc;
            float b0 = bsh[col], b1 = bsh[col + 1];
            int r0 = row_lo + mt * 16;
            int r1 = r0 + 8;
            if (r0 < M) {
                float2 o;
                o.x = c[mt][nt][0] + b0; o.x = o.x > 0.f ? o.x : 0.01f * o.x;
                o.y = c[mt][nt][1] + b1; o.y = o.y > 0.f ? o.y : 0.01f * o.y;
                *reinterpret_cast<float2*>(out + (size_t)r0 * D_N + col) = o;
            }
            if (r1 < M) {
                float2 o;
                o.x = c[mt][nt][2] + b0; o.x = o.x > 0.f ? o.x : 0.01f * o.x;
                o.y = c[mt][nt][3] + b1; o.y = o.y > 0.f ? o.y : 0.01f * o.y;
                *reinterpret_cast<float2*>(out + (size_t)r1 * D_N + col) = o;
            }
        }
    }
}

// ---------------- classification head ----------------
__global__ void head_kernel(const float* __restrict__ x, const float* __restrict__ Wh,
                            const float* __restrict__ bh, float* __restrict__ out) {
    __shared__ float wsh[NHEADS][128];
    __shared__ float bsh[NHEADS];
    int tid = threadIdx.x;
    for (int i = tid; i < NHEADS * 128; i += blockDim.x) wsh[i >> 7][i & 127] = Wh[i];
    if (tid < NHEADS) bsh[tid] = bh[tid];
    __syncthreads();

    int node = blockIdx.x * (blockDim.x >> 5) + (tid >> 5);
    int lane = tid & 31;
    if (node >= NB_N) return;
    float4 xv = *reinterpret_cast<const float4*>(x + (size_t)node * 128 + lane * 4);
    #pragma unroll
    for (int h = 0; h < NHEADS; ++h) {
        float4 wv = *reinterpret_cast<const float4*>(&wsh[h][lane * 4]);
        float p = xv.x * wv.x + xv.y * wv.y + xv.z * wv.z + xv.w * wv.w;
        #pragma unroll
        for (int o = 16; o > 0; o >>= 1) p += __shfl_down_sync(0xffffffffu, p, o);
        if (lane == 0) out[(size_t)node * NHEADS + h] = p + bsh[h];
    }
}

// ---------------- host launch ----------------
extern "C" void kernel_launch(void* const* d_in, const int* in_sizes, int n_in,
                              void* d_out, int out_size) {
    (void)in_sizes; (void)n_in; (void)out_size;
    const float* x_b  = (const float*)d_in[0];
    const float* x_s  = (const float*)d_in[1];
    const float* Wl   = (const float*)d_in[2];
    const float* bl   = (const float*)d_in[3];
    const float* Wr   = (const float*)d_in[4];
    const float* Wh   = (const float*)d_in[5];
    const float* bh   = (const float*)d_in[6];
    const int*   ei_bb = (const int*)d_in[7];   // JAX x64 off -> int32 indices
    const int*   ei_sb = (const int*)d_in[8];
    const int*   ei_bs = (const int*)d_in[9];

    void *p_xb0, *p_xb1, *p_xs0, *p_abb, *p_asb, *p_abs;
    void *p_Bb, *p_Bs, *p_FB, *p_FS;
    void *p_cnt_bb, *p_off_bb, *p_cur_bb, *p_perm_bb, *p_part_bb;
    void *p_cnt_sb, *p_off_sb, *p_cur_sb, *p_perm_sb, *p_part_sb;
    void *p_cnt_bs, *p_off_bs, *p_cur_bs, *p_perm_bs, *p_part_bs;
    cudaGetSymbolAddress(&p_xb0, g_xb0);  cudaGetSymbolAddress(&p_xb1, g_xb1);
    cudaGetSymbolAddress(&p_xs0, g_xs0);
    cudaGetSymbolAddress(&p_abb, g_acc_bb); cudaGetSymbolAddress(&p_asb, g_acc_sb);
    cudaGetSymbolAddress(&p_abs, g_acc_bs);
    cudaGetSymbolAddress(&p_Bb, g_Bb); cudaGetSymbolAddress(&p_Bs, g_Bs);
    cudaGetSymbolAddress(&p_FB, g_WfragB); cudaGetSymbolAddress(&p_FS, g_WfragS);
    cudaGetSymbolAddress(&p_cnt_bb, g_cnti_bb); cudaGetSymbolAddress(&p_off_bb, g_off_bb);
    cudaGetSymbolAddress(&p_cur_bb, g_cur_bb);  cudaGetSymbolAddress(&p_perm_bb, g_perm_bb);
    cudaGetSymbolAddress(&p_part_bb, g_part_bb);
    cudaGetSymbolAddress(&p_cnt_sb, g_cnti_sb); cudaGetSymbolAddress(&p_off_sb, g_off_sb);
    cudaGetSymbolAddress(&p_cur_sb, g_cur_sb);  cudaGetSymbolAddress(&p_perm_sb, g_perm_sb);
    cudaGetSymbolAddress(&p_part_sb, g_part_sb);
    cudaGetSymbolAddress(&p_cnt_bs, g_cnti_bs); cudaGetSymbolAddress(&p_off_bs, g_off_bs);
    cudaGetSymbolAddress(&p_cur_bs, g_cur_bs);  cudaGetSymbolAddress(&p_perm_bs, g_perm_bs);
    cudaGetSymbolAddress(&p_part_bs, g_part_bs);

    float* xb_buf[2] = {(float*)p_xb0, (float*)p_xb1};
    float* xs_buf    = (float*)p_xs0;
    float* acc_bb = (float*)p_abb; float* acc_sb = (float*)p_asb; float* acc_bs = (float*)p_abs;
    float* Bbp = (float*)p_Bb; float* Bsp = (float*)p_Bs;
    const uint4* FragB = (const uint4*)p_FB;
    const uint4* FragS = (const uint4*)p_FS;

    int* cnt_bb = (int*)p_cnt_bb; int* off_bb = (int*)p_off_bb; int* cur_bb = (int*)p_cur_bb;
    int* perm_bb = (int*)p_perm_bb; int* part_bb = (int*)p_part_bb;
    int* cnt_sb = (int*)p_cnt_sb; int* off_sb = (int*)p_off_sb; int* cur_sb = (int*)p_cur_sb;
    int* perm_sb = (int*)p_perm_sb; int* part_sb = (int*)p_part_sb;
    int* cnt_bs = (int*)p_cnt_bs; int* off_bs = (int*)p_off_bs; int* cur_bs = (int*)p_cur_bs;
    int* perm_bs = (int*)p_perm_bs; int* part_bs = (int*)p_part_bs;

    const int T = 256;
    const int NCH_B = (NB_N + SCHUNK - 1) / SCHUNK;   // 98
    const int NCH_S = (NS_N + SCHUNK - 1) / SCHUNK;   // 49

    // ---- weight prep ----
    prep_wb_kernel<<<(2 * 384 * 128 + T - 1) / T, T>>>(Wl, bl, Wr);
    prep_ws_kernel<<<(256 * 128 + T - 1) / T, T>>>(Wl, bl, Wr);
    prep_bfrag_b_kernel<<<(2 * 24 * 16 * 32 + T - 1) / T, T>>>();
    prep_bfrag_s_kernel<<<(16 * 16 * 32 + T - 1) / T, T>>>();

    // ---- CSR build (per edge type; edges constant across layers) ----
    zeroi_kernel<<<(NB_N / 4 + T - 1) / T, T>>>((int4*)cnt_bb, NB_N / 4);
    zeroi_kernel<<<(NB_N / 4 + T - 1) / T, T>>>((int4*)cnt_sb, NB_N / 4);
    zeroi_kernel<<<(NS_N / 4 + T - 1) / T, T>>>((int4*)cnt_bs, NS_N / 4);
    counti_kernel<<<(E_BB_N + T - 1) / T, T>>>(ei_bb + E_BB_N, cnt_bb, E_BB_N);
    counti_kernel<<<(E_SB_N + T - 1) / T, T>>>(ei_sb + E_SB_N, cnt_sb, E_SB_N);
    counti_kernel<<<(E_BS_N + T - 1) / T, T>>>(ei_bs + E_BS_N, cnt_bs, E_BS_N);

    scanA_kernel<<<NCH_B, SCHUNK>>>(cnt_bb, part_bb, NB_N);
    scanA_kernel<<<NCH_B, SCHUNK>>>(cnt_sb, part_sb, NB_N);
    scanA_kernel<<<NCH_S, SCHUNK>>>(cnt_bs, part_bs, NS_N);
    scanB_kernel<<<1, 128>>>(part_bb, NCH_B);
    scanB_kernel<<<1, 128>>>(part_sb, NCH_B);
    scanB_kernel<<<1, 128>>>(part_bs, NCH_S);
    scanC_kernel<<<NCH_B, SCHUNK>>>(cnt_bb, part_bb, off_bb, cur_bb, NB_N);
    scanC_kernel<<<NCH_B, SCHUNK>>>(cnt_sb, part_sb, off_sb, cur_sb, NB_N);
    scanC_kernel<<<NCH_S, SCHUNK>>>(cnt_bs, part_bs, off_bs, cur_bs, NS_N);

    fill_kernel<<<(E_BB_N + T - 1) / T, T>>>(ei_bb, ei_bb + E_BB_N, cur_bb, perm_bb, E_BB_N);
    fill_kernel<<<(E_SB_N + T - 1) / T, T>>>(ei_sb, ei_sb + E_SB_N, cur_sb, perm_sb, E_SB_N);
    fill_kernel<<<(E_BS_N + T - 1) / T, T>>>(ei_bs, ei_bs + E_BS_N, cur_bs, perm_bs, E_BS_N);

    const float* cur_b = x_b;
    const float* cur_s = x_s;

    for (int l = 0; l < 2; ++l) {
        // segmented means (write every row -> no zeroing needed)
        segmean_kernel<<<(NB_N + 7) / 8, 256>>>(cur_b, perm_bb, off_bb, cnt_bb, acc_bb, NB_N);
        segmean_kernel<<<(NB_N + 7) / 8, 256>>>(cur_s, perm_sb, off_sb, cnt_sb, acc_sb, NB_N);
        if (l == 0)
            segmean_kernel<<<(NS_N + 7) / 8, 256>>>(cur_b, perm_bs, off_bs, cnt_bs, acc_bs, NS_N);

        float* next_b = xb_buf[l];
        gemm_mma_kernel<<<(NB_N + 127) / 128, 256>>>(
            acc_bb, acc_sb, cur_b,
            FragB + (size_t)l * 24 * 16 * 32, Bbp + (size_t)l * 128,
            next_b, NB_N, 3);
        if (l == 0) {
            // layer-2 x_s update is dead code (never reaches output) — only layer-1
            gemm_mma_kernel<<<(NS_N + 127) / 128, 256>>>(
                acc_bs, cur_s, nullptr,
                FragS, Bsp,
                xs_buf, NS_N, 2);
            cur_s = xs_buf;
        }
        cur_b = next_b;
    }

    head_kernel<<<(NB_N + 7) / 8, 256>>>(cur_b, Wh, bh, (float*)d_out);
}

// round 8
// speedup vs baseline: 2.3101x; 1.3946x over previous
#include <cuda_runtime.h>
#include <cuda_bf16.h>
#include <cstdint>
#include <cstddef>

// ---------------- problem constants ----------------
#define NB_N   100000
#define NS_N   50000
#define D_N    128
#define NHEADS 8
#define E_BB_N 800000
#define E_SB_N 400000
#define E_BS_N 400000

// ---------------- device scratch (static; no allocation) ----------------
__device__ float g_xb0[(size_t)NB_N * D_N];
__device__ float g_xs0[(size_t)NS_N * D_N];

__device__ float g_acc_bb[(size_t)NB_N * D_N];   // per-dst MEAN after segmean
__device__ float g_acc_sb[(size_t)NB_N * D_N];
__device__ float g_acc_bs[(size_t)NS_N * D_N];

// CSR structures per edge type
__device__ int g_cnti_bb[NB_N];
__device__ int g_off_bb[NB_N];
__device__ int g_cur_bb[NB_N];
__device__ int g_perm_bb[E_BB_N];
__device__ int g_cnti_sb[NB_N];
__device__ int g_off_sb[NB_N];
__device__ int g_cur_sb[NB_N];
__device__ int g_perm_sb[E_SB_N];
__device__ int g_cnti_bs[NS_N];
__device__ int g_off_bs[NS_N];
__device__ int g_cur_bs[NS_N];
__device__ int g_perm_bs[E_BS_N];

// dedicated scan-partial buffers (MUST NOT alias cur)
__device__ int g_part_bb[128];
__device__ int g_part_sb[128];
__device__ int g_part_bs[128];

// combined fp32 weights: b-dst [2][384][128] (k-major), s-dst layer0 [256][128]
__device__ float g_Wb[2][384 * 128];
__device__ float g_Bb[2][128];
__device__ float g_Ws[256 * 128];
__device__ float g_Bs[128];

// B in HMMA fragment order: per (ktile, ntile, lane) a uint4 {hi_b0, hi_b1, lo_b0, lo_b1}
__device__ uint4 g_WfragB[2 * 24 * 16 * 32];
__device__ uint4 g_WfragS[16 * 16 * 32];

// ---------------- split-bf16 pack: hi = truncate-to-bf16, lo = RN(residual) ----------------
__device__ __forceinline__ void split_pack(float v0, float v1, uint32_t& hp, uint32_t& lp) {
    uint32_t b0 = __float_as_uint(v0), b1 = __float_as_uint(v1);
    hp = (b1 & 0xFFFF0000u) | (b0 >> 16);
    float h0 = __uint_as_float(b0 & 0xFFFF0000u);
    float h1 = __uint_as_float(b1 & 0xFFFF0000u);
    asm("cvt.rn.bf16x2.f32 %0, %1, %2;" : "=r"(lp) : "f"(v1 - h1), "f"(v0 - h0));
}

__device__ __forceinline__ void mma_bf16(float* c, const uint32_t* a, uint32_t b0, uint32_t b1) {
    asm volatile("mma.sync.aligned.m16n8k16.row.col.f32.bf16.bf16.f32 "
                 "{%0,%1,%2,%3}, {%4,%5,%6,%7}, {%8,%9}, {%0,%1,%2,%3};"
                 : "+f"(c[0]), "+f"(c[1]), "+f"(c[2]), "+f"(c[3])
                 : "r"(a[0]), "r"(a[1]), "r"(a[2]), "r"(a[3]), "r"(b0), "r"(b1));
}

// ---------------- CSR build kernels ----------------
__global__ void zeroi_kernel(int4* __restrict__ p, int n4) {
    int i = blockIdx.x * blockDim.x + threadIdx.x;
    if (i < n4) p[i] = make_int4(0, 0, 0, 0);
}
__global__ void counti_kernel(const int* __restrict__ dst, int* __restrict__ cnt, int E) {
    int e = blockIdx.x * blockDim.x + threadIdx.x;
    if (e < E) atomicAdd(cnt + dst[e], 1);
}

#define SCHUNK 1024
__global__ void scanA_kernel(const int* __restrict__ cnt, int* __restrict__ part, int n) {
    __shared__ int sh[SCHUNK];
    int t = threadIdx.x;
    int i = blockIdx.x * SCHUNK + t;
    sh[t] = (i < n) ? cnt[i] : 0;
    __syncthreads();
    #pragma unroll
    for (int s = 512; s > 0; s >>= 1) {
        if (t < s) sh[t] += sh[t + s];
        __syncthreads();
    }
    if (t == 0) part[blockIdx.x] = sh[0];
}
__global__ void scanB_kernel(int* __restrict__ part, int nb) {
    __shared__ int sh[128];
    int t = threadIdx.x;
    int v = (t < nb) ? part[t] : 0;
    sh[t] = v;
    __syncthreads();
    #pragma unroll
    for (int s = 1; s < 128; s <<= 1) {
        int a = (t >= s) ? sh[t - s] : 0;
        __syncthreads();
        sh[t] += a;
        __syncthreads();
    }
    if (t < nb) part[t] = sh[t] - v;
}
__global__ void scanC_kernel(const int* __restrict__ cnt, const int* __restrict__ part,
                             int* __restrict__ off, int* __restrict__ cur, int n) {
    __shared__ int sh[SCHUNK];
    int t = threadIdx.x;
    int i = blockIdx.x * SCHUNK + t;
    int v = (i < n) ? cnt[i] : 0;
    sh[t] = v;
    __syncthreads();
    #pragma unroll
    for (int s = 1; s < SCHUNK; s <<= 1) {
        int a = (t >= s) ? sh[t - s] : 0;
        __syncthreads();
        sh[t] += a;
        __syncthreads();
    }
    if (i < n) {
        int ex = sh[t] - v + part[blockIdx.x];
        off[i] = ex;
        cur[i] = ex;
    }
}
__global__ void fill_kernel(const int* __restrict__ src, const int* __restrict__ dst,
                            int* __restrict__ cur, int* __restrict__ perm, int E) {
    int e = blockIdx.x * blockDim.x + threadIdx.x;
    if (e < E) {
        int p = atomicAdd(cur + dst[e], 1);
        perm[p] = src[e];
    }
}

// ---------------- segmented mean core (warp per node, 8-deep MLP) ----------------
__device__ __forceinline__ void segmean_row(const float* __restrict__ x,
                                            const int* __restrict__ perm,
                                            int o, int c, int lane,
                                            float* __restrict__ outrow) {
    float4 acc = make_float4(0.f, 0.f, 0.f, 0.f);
    int i = 0;
    for (; i + 8 <= c; i += 8) {
        float4 v[8];
        #pragma unroll
        for (int j = 0; j < 8; ++j) {
            int s = perm[o + i + j];
            v[j] = reinterpret_cast<const float4*>(x + (size_t)s * D_N)[lane];
        }
        #pragma unroll
        for (int j = 0; j < 8; ++j) {
            acc.x += v[j].x; acc.y += v[j].y; acc.z += v[j].z; acc.w += v[j].w;
        }
    }
    for (; i + 4 <= c; i += 4) {
        float4 v[4];
        #pragma unroll
        for (int j = 0; j < 4; ++j) {
            int s = perm[o + i + j];
            v[j] = reinterpret_cast<const float4*>(x + (size_t)s * D_N)[lane];
        }
        #pragma unroll
        for (int j = 0; j < 4; ++j) {
            acc.x += v[j].x; acc.y += v[j].y; acc.z += v[j].z; acc.w += v[j].w;
        }
    }
    for (; i < c; ++i) {
        int s = perm[o + i];
        float4 v = reinterpret_cast<const float4*>(x + (size_t)s * D_N)[lane];
        acc.x += v.x; acc.y += v.y; acc.z += v.z; acc.w += v.w;
    }
    float inv = (c > 0) ? 1.0f / (float)c : 0.0f;
    acc.x *= inv; acc.y *= inv; acc.z *= inv; acc.w *= inv;
    reinterpret_cast<float4*>(outrow)[lane] = acc;
}

// merged bb + sb segmean: warps [0,NB) -> bb (src x_b), [NB,2NB) -> sb (src x_s)
__global__ void __launch_bounds__(256)
segmean2_kernel(const float* __restrict__ xb, const float* __restrict__ xs,
                const int* __restrict__ perm_bb, const int* __restrict__ off_bb,
                const int* __restrict__ cnt_bb,
                const int* __restrict__ perm_sb, const int* __restrict__ off_sb,
                const int* __restrict__ cnt_sb,
                float* __restrict__ acc_bb, float* __restrict__ acc_sb) {
    int w    = (blockIdx.x * blockDim.x + threadIdx.x) >> 5;
    int lane = threadIdx.x & 31;
    if (w < NB_N) {
        segmean_row(xb, perm_bb, off_bb[w], cnt_bb[w], lane, acc_bb + (size_t)w * D_N);
    } else if (w < 2 * NB_N) {
        int u = w - NB_N;
        segmean_row(xs, perm_sb, off_sb[u], cnt_sb[u], lane, acc_sb + (size_t)u * D_N);
    }
}

__global__ void __launch_bounds__(256)
segmean_kernel(const float* __restrict__ x, const int* __restrict__ perm,
               const int* __restrict__ off, const int* __restrict__ cnti,
               float* __restrict__ out, int n) {
    int w    = (blockIdx.x * blockDim.x + threadIdx.x) >> 5;
    int lane = threadIdx.x & 31;
    if (w >= n) return;
    segmean_row(x, perm, off[w], cnti[w], lane, out + (size_t)w * D_N);
}

// ---------------- weight prep ----------------
__global__ void prep_wb_kernel(const float* __restrict__ Wl, const float* __restrict__ bl,
                               const float* __restrict__ Wr) {
    int idx = blockIdx.x * blockDim.x + threadIdx.x;
    const int total = 2 * 384 * 128;
    if (idx < total) {
        int l = idx / (384 * 128);
        int r = idx % (384 * 128);
        int k = r / 128, n = r % 128;
        float v;
        if (k < 128)      v = Wl[((size_t)(l * 3 + 0) * 128 + k) * 128 + n];
        else if (k < 256) v = Wl[((size_t)(l * 3 + 1) * 128 + (k - 128)) * 128 + n];
        else              v = Wr[((size_t)(l * 3 + 0) * 128 + (k - 256)) * 128 + n]
                            + Wr[((size_t)(l * 3 + 1) * 128 + (k - 256)) * 128 + n];
        g_Wb[l][r] = v;
    }
    if (idx < 2 * 128) {
        int l = idx / 128, n = idx % 128;
        g_Bb[l][n] = bl[(l * 3 + 0) * 128 + n] + bl[(l * 3 + 1) * 128 + n];
    }
}
__global__ void prep_ws_kernel(const float* __restrict__ Wl, const float* __restrict__ bl,
                               const float* __restrict__ Wr) {
    int idx = blockIdx.x * blockDim.x + threadIdx.x;
    const int total = 256 * 128;
    if (idx < total) {
        int k = idx / 128, n = idx % 128;
        float v;
        if (k < 128) v = Wl[((size_t)2 * 128 + k) * 128 + n];
        else         v = Wr[((size_t)2 * 128 + (k - 128)) * 128 + n];
        g_Ws[idx] = v;
    }
    if (idx < 128) g_Bs[idx] = bl[2 * 128 + idx];
}
__global__ void prep_bfrag_b_kernel() {
    int idx = blockIdx.x * blockDim.x + threadIdx.x;
    if (idx >= 2 * 24 * 16 * 32) return;
    int lane = idx & 31;
    int nt   = (idx >> 5) & 15;
    int t    = idx >> 9;
    int kt   = t % 24;
    int l    = t / 24;
    int n  = nt * 8 + (lane >> 2);
    int k0 = kt * 16 + (lane & 3) * 2;
    const float* W = g_Wb[l];
    float v0 = W[(k0 + 0) * 128 + n], v1 = W[(k0 + 1) * 128 + n];
    float v8 = W[(k0 + 8) * 128 + n], v9 = W[(k0 + 9) * 128 + n];
    uint32_t h0, l0, h1, l1;
    split_pack(v0, v1, h0, l0);
    split_pack(v8, v9, h1, l1);
    g_WfragB[idx] = make_uint4(h0, h1, l0, l1);
}
__global__ void prep_bfrag_s_kernel() {
    int idx = blockIdx.x * blockDim.x + threadIdx.x;
    if (idx >= 16 * 16 * 32) return;
    int lane = idx & 31;
    int nt   = (idx >> 5) & 15;
    int kt   = idx >> 9;
    int n  = nt * 8 + (lane >> 2);
    int k0 = kt * 16 + (lane & 3) * 2;
    float v0 = g_Ws[(k0 + 0) * 128 + n], v1 = g_Ws[(k0 + 1) * 128 + n];
    float v8 = g_Ws[(k0 + 8) * 128 + n], v9 = g_Ws[(k0 + 9) * 128 + n];
    uint32_t h0, l0, h1, l1;
    split_pack(v0, v1, h0, l0);
    split_pack(v8, v9, h1, l1);
    g_WfragS[idx] = make_uint4(h0, h1, l0, l1);
}

// ---------------- HMMA fused segmented GEMM + bias + leaky_relu (+ optional head) ----------------
// block: 256 rows x 128 cols; 8 warps stacked in M; warp tile 32x128 (A loaded once).
// if head_out != nullptr: epilogue computes leaky features in-register and writes
// only the 8-head readout (layer-2 b path). Otherwise writes fp32 features to out.
__device__ __forceinline__ void load_rawA(const float* __restrict__ A0,
                                          const float* __restrict__ A1,
                                          const float* __restrict__ A2,
                                          int kt, int row_lo, int lc, int M,
                                          float2 (&xa)[2][2], float2 (&xb)[2][2]) {
    const int seg = kt >> 3;
    const int kk  = (kt & 7) * 16;
    const float* A = (seg == 0) ? A0 : ((seg == 1) ? A1 : A2);
    #pragma unroll
    for (int mt = 0; mt < 2; ++mt)
        #pragma unroll
        for (int half = 0; half < 2; ++half) {
            int r = row_lo + mt * 16 + half * 8;
            float2 v0 = make_float2(0.f, 0.f), v1 = v0;
            if (r < M) {
                const float* p = A + (size_t)r * D_N + kk + lc;
                v0 = *reinterpret_cast<const float2*>(p);
                v1 = *reinterpret_cast<const float2*>(p + 8);
            }
            xa[mt][half] = v0;
            xb[mt][half] = v1;
        }
}

__global__ void __launch_bounds__(256)
gemm_mma_kernel(const float* __restrict__ A0, const float* __restrict__ A1,
                const float* __restrict__ A2,
                const uint4* __restrict__ Bfrag, const float* __restrict__ bias,
                float* __restrict__ out, int M, int nseg,
                const float* __restrict__ Wh, const float* __restrict__ bh,
                float* __restrict__ head_out) {
    __shared__ float bsh[128];
    __shared__ float wsh[NHEADS][128];
    __shared__ float bhs[NHEADS];

    const int tid  = threadIdx.x;
    const int lane = tid & 31;
    const int wid  = tid >> 5;
    const int row0 = blockIdx.x * 256;

    if (tid < 128) bsh[tid] = bias[tid];
    if (head_out) {
        for (int i = tid; i < NHEADS * 128; i += 256) wsh[i >> 7][i & 127] = Wh[i];
        if (tid < NHEADS) bhs[tid] = bh[tid];
    }
    __syncthreads();

    const int lr  = lane >> 2;
    const int lc  = (lane & 3) * 2;
    const int row_lo = row0 + wid * 32 + lr;

    float c[2][16][4] = {};
    const int K16 = nseg * 8;

    float2 ra[2][2], rb[2][2], na[2][2], nb[2][2];
    load_rawA(A0, A1, A2, 0, row_lo, lc, M, ra, rb);

    for (int kt = 0; kt < K16; ++kt) {
        if (kt + 1 < K16)
            load_rawA(A0, A1, A2, kt + 1, row_lo, lc, M, na, nb);

        uint32_t ah[2][4], al[2][4];
        #pragma unroll
        for (int mt = 0; mt < 2; ++mt)
            #pragma unroll
            for (int half = 0; half < 2; ++half) {
                split_pack(ra[mt][half].x, ra[mt][half].y, ah[mt][half], al[mt][half]);
                split_pack(rb[mt][half].x, rb[mt][half].y, ah[mt][2 + half], al[mt][2 + half]);
            }

        const uint4* bp = Bfrag + (size_t)kt * 16 * 32 + lane;
        #pragma unroll
        for (int nt = 0; nt < 16; ++nt) {
            uint4 b = bp[nt * 32];
            #pragma unroll
            for (int mt = 0; mt < 2; ++mt) {
                mma_bf16(c[mt][nt], ah[mt], b.x, b.y);
                mma_bf16(c[mt][nt], al[mt], b.x, b.y);
                mma_bf16(c[mt][nt], ah[mt], b.z, b.w);
            }
        }

        #pragma unroll
        for (int mt = 0; mt < 2; ++mt)
            #pragma unroll
            for (int half = 0; half < 2; ++half) {
                ra[mt][half] = na[mt][half];
                rb[mt][half] = nb[mt][half];
            }
    }

    if (head_out) {
        // fused readout: leaky(c + bias) dotted with 8 head vectors
        #pragma unroll
        for (int mt = 0; mt < 2; ++mt) {
            #pragma unroll
            for (int half = 0; half < 2; ++half) {
                int r = row_lo + mt * 16 + half * 8;
                float hp[NHEADS] = {};
                #pragma unroll
                for (int nt = 0; nt < 16; ++nt) {
                    int col = nt * 8 + lc;
                    float v0 = c[mt][nt][half * 2 + 0] + bsh[col];
                    float v1 = c[mt][nt][half * 2 + 1] + bsh[col + 1];
                    v0 = v0 > 0.f ? v0 : 0.01f * v0;
                    v1 = v1 > 0.f ? v1 : 0.01f * v1;
                    #pragma unroll
                    for (int h = 0; h < NHEADS; ++h)
                        hp[h] += v0 * wsh[h][col] + v1 * wsh[h][col + 1];
                }
                #pragma unroll
                for (int h = 0; h < NHEADS; ++h) {
                    hp[h] += __shfl_down_sync(0xffffffffu, hp[h], 2, 4);
                    hp[h] += __shfl_down_sync(0xffffffffu, hp[h], 1, 4);
                }
                if ((lane & 3) == 0 && r < M) {
                    float4 o0 = make_float4(hp[0] + bhs[0], hp[1] + bhs[1],
                                            hp[2] + bhs[2], hp[3] + bhs[3]);
                    float4 o1 = make_float4(hp[4] + bhs[4], hp[5] + bhs[5],
                                            hp[6] + bhs[6], hp[7] + bhs[7]);
                    *reinterpret_cast<float4*>(head_out + (size_t)r * NHEADS)     = o0;
                    *reinterpret_cast<float4*>(head_out + (size_t)r * NHEADS + 4) = o1;
                }
            }
        }
    } else {
        #pragma unroll
        for (int mt = 0; mt < 2; ++mt) {
            #pragma unroll
            for (int nt = 0; nt < 16; ++nt) {
                int col = nt * 8 + lc;
                float b0 = bsh[col], b1 = bsh[col + 1];
                int r0 = row_lo + mt * 16;
                int r1 = r0 + 8;
                if (r0 < M) {
                    float2 o;
                    o.x = c[mt][nt][0] + b0; o.x = o.x > 0.f ? o.x : 0.01f * o.x;
                    o.y = c[mt][nt][1] + b1; o.y = o.y > 0.f ? o.y : 0.01f * o.y;
                    *reinterpret_cast<float2*>(out + (size_t)r0 * D_N + col) = o;
                }
                if (r1 < M) {
                    float2 o;
                    o.x = c[mt][nt][2] + b0; o.x = o.x > 0.f ? o.x : 0.01f * o.x;
                    o.y = c[mt][nt][3] + b1; o.y = o.y > 0.f ? o.y : 0.01f * o.y;
                    *reinterpret_cast<float2*>(out + (size_t)r1 * D_N + col) = o;
                }
            }
        }
    }
}

// ---------------- host launch ----------------
extern "C" void kernel_launch(void* const* d_in, const int* in_sizes, int n_in,
                              void* d_out, int out_size) {
    (void)in_sizes; (void)n_in; (void)out_size;
    const float* x_b  = (const float*)d_in[0];
    const float* x_s  = (const float*)d_in[1];
    const float* Wl   = (const float*)d_in[2];
    const float* bl   = (const float*)d_in[3];
    const float* Wr   = (const float*)d_in[4];
    const float* Wh   = (const float*)d_in[5];
    const float* bh   = (const float*)d_in[6];
    const int*   ei_bb = (const int*)d_in[7];   // JAX x64 off -> int32 indices
    const int*   ei_sb = (const int*)d_in[8];
    const int*   ei_bs = (const int*)d_in[9];

    void *p_xb0, *p_xs0, *p_abb, *p_asb, *p_abs;
    void *p_Bb, *p_Bs, *p_FB, *p_FS;
    void *p_cnt_bb, *p_off_bb, *p_cur_bb, *p_perm_bb, *p_part_bb;
    void *p_cnt_sb, *p_off_sb, *p_cur_sb, *p_perm_sb, *p_part_sb;
    void *p_cnt_bs, *p_off_bs, *p_cur_bs, *p_perm_bs, *p_part_bs;
    cudaGetSymbolAddress(&p_xb0, g_xb0);
    cudaGetSymbolAddress(&p_xs0, g_xs0);
    cudaGetSymbolAddress(&p_abb, g_acc_bb); cudaGetSymbolAddress(&p_asb, g_acc_sb);
    cudaGetSymbolAddress(&p_abs, g_acc_bs);
    cudaGetSymbolAddress(&p_Bb, g_Bb); cudaGetSymbolAddress(&p_Bs, g_Bs);
    cudaGetSymbolAddress(&p_FB, g_WfragB); cudaGetSymbolAddress(&p_FS, g_WfragS);
    cudaGetSymbolAddress(&p_cnt_bb, g_cnti_bb); cudaGetSymbolAddress(&p_off_bb, g_off_bb);
    cudaGetSymbolAddress(&p_cur_bb, g_cur_bb);  cudaGetSymbolAddress(&p_perm_bb, g_perm_bb);
    cudaGetSymbolAddress(&p_part_bb, g_part_bb);
    cudaGetSymbolAddress(&p_cnt_sb, g_cnti_sb); cudaGetSymbolAddress(&p_off_sb, g_off_sb);
    cudaGetSymbolAddress(&p_cur_sb, g_cur_sb);  cudaGetSymbolAddress(&p_perm_sb, g_perm_sb);
    cudaGetSymbolAddress(&p_part_sb, g_part_sb);
    cudaGetSymbolAddress(&p_cnt_bs, g_cnti_bs); cudaGetSymbolAddress(&p_off_bs, g_off_bs);
    cudaGetSymbolAddress(&p_cur_bs, g_cur_bs);  cudaGetSymbolAddress(&p_perm_bs, g_perm_bs);
    cudaGetSymbolAddress(&p_part_bs, g_part_bs);

    float* xb0 = (float*)p_xb0;
    float* xs0 = (float*)p_xs0;
    float* acc_bb = (float*)p_abb; float* acc_sb = (float*)p_asb; float* acc_bs = (float*)p_abs;
    float* Bbp = (float*)p_Bb; float* Bsp = (float*)p_Bs;
    const uint4* FragB = (const uint4*)p_FB;
    const uint4* FragS = (const uint4*)p_FS;

    int* cnt_bb = (int*)p_cnt_bb; int* off_bb = (int*)p_off_bb; int* cur_bb = (int*)p_cur_bb;
    int* perm_bb = (int*)p_perm_bb; int* part_bb = (int*)p_part_bb;
    int* cnt_sb = (int*)p_cnt_sb; int* off_sb = (int*)p_off_sb; int* cur_sb = (int*)p_cur_sb;
    int* perm_sb = (int*)p_perm_sb; int* part_sb = (int*)p_part_sb;
    int* cnt_bs = (int*)p_cnt_bs; int* off_bs = (int*)p_off_bs; int* cur_bs = (int*)p_cur_bs;
    int* perm_bs = (int*)p_perm_bs; int* part_bs = (int*)p_part_bs;

    const int T = 256;
    const int NCH_B = (NB_N + SCHUNK - 1) / SCHUNK;   // 98
    const int NCH_S = (NS_N + SCHUNK - 1) / SCHUNK;   // 49

    // ---- weight prep ----
    prep_wb_kernel<<<(2 * 384 * 128 + T - 1) / T, T>>>(Wl, bl, Wr);
    prep_ws_kernel<<<(256 * 128 + T - 1) / T, T>>>(Wl, bl, Wr);
    prep_bfrag_b_kernel<<<(2 * 24 * 16 * 32 + T - 1) / T, T>>>();
    prep_bfrag_s_kernel<<<(16 * 16 * 32 + T - 1) / T, T>>>();

    // ---- CSR build ----
    zeroi_kernel<<<(NB_N / 4 + T - 1) / T, T>>>((int4*)cnt_bb, NB_N / 4);
    zeroi_kernel<<<(NB_N / 4 + T - 1) / T, T>>>((int4*)cnt_sb, NB_N / 4);
    zeroi_kernel<<<(NS_N / 4 + T - 1) / T, T>>>((int4*)cnt_bs, NS_N / 4);
    counti_kernel<<<(E_BB_N + T - 1) / T, T>>>(ei_bb + E_BB_N, cnt_bb, E_BB_N);
    counti_kernel<<<(E_SB_N + T - 1) / T, T>>>(ei_sb + E_SB_N, cnt_sb, E_SB_N);
    counti_kernel<<<(E_BS_N + T - 1) / T, T>>>(ei_bs + E_BS_N, cnt_bs, E_BS_N);

    scanA_kernel<<<NCH_B, SCHUNK>>>(cnt_bb, part_bb, NB_N);
    scanA_kernel<<<NCH_B, SCHUNK>>>(cnt_sb, part_sb, NB_N);
    scanA_kernel<<<NCH_S, SCHUNK>>>(cnt_bs, part_bs, NS_N);
    scanB_kernel<<<1, 128>>>(part_bb, NCH_B);
    scanB_kernel<<<1, 128>>>(part_sb, NCH_B);
    scanB_kernel<<<1, 128>>>(part_bs, NCH_S);
    scanC_kernel<<<NCH_B, SCHUNK>>>(cnt_bb, part_bb, off_bb, cur_bb, NB_N);
    scanC_kernel<<<NCH_B, SCHUNK>>>(cnt_sb, part_sb, off_sb, cur_sb, NB_N);
    scanC_kernel<<<NCH_S, SCHUNK>>>(cnt_bs, part_bs, off_bs, cur_bs, NS_N);

    fill_kernel<<<(E_BB_N + T - 1) / T, T>>>(ei_bb, ei_bb + E_BB_N, cur_bb, perm_bb, E_BB_N);
    fill_kernel<<<(E_SB_N + T - 1) / T, T>>>(ei_sb, ei_sb + E_SB_N, cur_sb, perm_sb, E_SB_N);
    fill_kernel<<<(E_BS_N + T - 1) / T, T>>>(ei_bs, ei_bs + E_BS_N, cur_bs, perm_bs, E_BS_N);

    const float* cur_b = x_b;
    const float* cur_s = x_s;

    for (int l = 0; l < 2; ++l) {
        // merged bb+sb segmean (writes every row -> no zeroing needed)
        segmean2_kernel<<<(2 * NB_N + 7) / 8, 256>>>(
            cur_b, cur_s, perm_bb, off_bb, cnt_bb, perm_sb, off_sb, cnt_sb,
            acc_bb, acc_sb);
        if (l == 0)
            segmean_kernel<<<(NS_N + 7) / 8, 256>>>(cur_b, perm_bs, off_bs, cnt_bs, acc_bs, NS_N);

        if (l == 0) {
            gemm_mma_kernel<<<(NB_N + 255) / 256, 256>>>(
                acc_bb, acc_sb, cur_b,
                FragB, Bbp,
                xb0, NB_N, 3, nullptr, nullptr, nullptr);
            // layer-2 x_s update is dead code (never reaches output) — only layer-1
            gemm_mma_kernel<<<(NS_N + 255) / 256, 256>>>(
                acc_bs, cur_s, nullptr,
                FragS, Bsp,
                xs0, NS_N, 2, nullptr, nullptr, nullptr);
            cur_s = xs0;
            cur_b = xb0;
        } else {
            // layer-2 b path: features consumed only by the head -> fused readout
            gemm_mma_kernel<<<(NB_N + 255) / 256, 256>>>(
                acc_bb, acc_sb, cur_b,
                FragB + (size_t)24 * 16 * 32, Bbp + 128,
                nullptr, NB_N, 3, Wh, bh, (float*)d_out);
        }
    }
}